// round 4
// baseline (speedup 1.0000x reference)
#include <cuda_runtime.h>
#include <math.h>

#define NN     50000
#define NE     800000
#define INCH   128
#define HH     256      // HEADS*HID
#define NHEAD  4
#define HID    64
#define GG     64
#define DCAT   640      // 128 + 256 + 256
#define NEG    0.2f

// ---------------- scratch (static device globals; no allocation) ----------------
__device__ float g_lin[(size_t)NN * HH];   // x@W (pre-attention features)
__device__ float g_h1 [(size_t)NN * HH];   // layer-1 output (post relu+bias)
__device__ float g_h2 [(size_t)NN * HH];   // layer-2 output
__device__ float g_es [NN * NHEAD];        // per-node src logits
__device__ float g_ed [NN * NHEAD];        // per-node dst logits
__device__ int   g_deg[NN];
__device__ int   g_off[NN + 1];
__device__ int   g_cur[NN];
__device__ int   g_csr_src[NE];            // src node id, grouped by dst
__device__ float g_pool[GG * DCAT];
__device__ float g_cnt [GG];

// ---------------- small setup kernels ----------------
__global__ void k_zero() {
    int i = blockIdx.x * blockDim.x + threadIdx.x;
    if (i < NN) g_deg[i] = 0;
    if (i < GG * DCAT) g_pool[i] = 0.f;
    if (i < GG) g_cnt[i] = 0.f;
}

__global__ void k_hist(const int* __restrict__ ei) {
    int e = blockIdx.x * blockDim.x + threadIdx.x;
    if (e < NE) {
        int d = ei[NE + e];
        atomicAdd(&g_deg[d], 1);
    }
}

// single-block exclusive scan over g_deg -> g_off, g_cur
__global__ void k_scan() {
    __shared__ int sm[1024];
    __shared__ int carry;
    int t = threadIdx.x;
    if (t == 0) carry = 0;
    __syncthreads();
    for (int base = 0; base < NN; base += 1024) {
        int v = (base + t < NN) ? g_deg[base + t] : 0;
        sm[t] = v;
        __syncthreads();
        #pragma unroll
        for (int o = 1; o < 1024; o <<= 1) {
            int a = (t >= o) ? sm[t - o] : 0;
            __syncthreads();
            sm[t] += a;
            __syncthreads();
        }
        int excl = sm[t] - v;
        if (base + t < NN) {
            g_off[base + t] = carry + excl;
            g_cur[base + t] = carry + excl;
        }
        __syncthreads();
        if (t == 1023) carry += sm[1023];
        __syncthreads();
    }
    if (t == 0) g_off[NN] = carry;
}

__global__ void k_scatter(const int* __restrict__ ei) {
    int e = blockIdx.x * blockDim.x + threadIdx.x;
    if (e < NE) {
        int s = ei[e];
        int d = ei[NE + e];
        int p = atomicAdd(&g_cur[d], 1);
        g_csr_src[p] = s;
    }
}

// ---------------- GEMM: out[N,256] = X[N,K] @ W[K,256] ----------------
// block = 256 threads; tile 64 rows x 256 cols; thread = 16 rows x 4 cols
template<int K>
__global__ void __launch_bounds__(256) k_gemm(const float* __restrict__ X,
                                              const float* __restrict__ W,
                                              float* __restrict__ out) {
    extern __shared__ float xs[];            // [64][K]
    int t = threadIdx.x;
    int rowbase = blockIdx.x * 64;
    for (int i = t; i < 64 * K; i += 256) {
        int r = i / K;
        int k = i - r * K;
        int gr = rowbase + r;
        xs[i] = (gr < NN) ? X[(size_t)gr * K + k] : 0.f;
    }
    __syncthreads();

    int cg = t & 63;     // col group: cols cg*4 .. cg*4+3
    int rg = t >> 6;     // row group: rows rg*16 .. rg*16+15

    float acc[16][4];
    #pragma unroll
    for (int r = 0; r < 16; r++)
        #pragma unroll
        for (int c = 0; c < 4; c++) acc[r][c] = 0.f;

    const float4* Wv = (const float4*)W;
    const float* xb = xs + rg * 16 * K;

    #pragma unroll 4
    for (int k = 0; k < K; k++) {
        float4 w = __ldg(&Wv[k * 64 + cg]);
        #pragma unroll
        for (int r = 0; r < 16; r++) {
            float xv = xb[r * K + k];
            acc[r][0] += xv * w.x;
            acc[r][1] += xv * w.y;
            acc[r][2] += xv * w.z;
            acc[r][3] += xv * w.w;
        }
    }

    #pragma unroll
    for (int r = 0; r < 16; r++) {
        int row = rowbase + rg * 16 + r;
        if (row < NN) {
            float4 o = make_float4(acc[r][0], acc[r][1], acc[r][2], acc[r][3]);
            ((float4*)(out + (size_t)row * HH))[cg] = o;
        }
    }
}

// ---------------- attention logits: e_src/e_dst per node ----------------
__global__ void k_logits(const float* __restrict__ lin,
                         const float* __restrict__ asrc,
                         const float* __restrict__ adst) {
    int w = (blockIdx.x * blockDim.x + threadIdx.x) >> 5;
    if (w >= NN) return;
    int lane = threadIdx.x & 31;

    const float4* lp = (const float4*)(lin + (size_t)w * HH);
    float4 v0 = lp[lane * 2], v1 = lp[lane * 2 + 1];
    const float4* ap = (const float4*)asrc;
    const float4* bp = (const float4*)adst;
    float4 a0 = __ldg(&ap[lane * 2]), a1 = __ldg(&ap[lane * 2 + 1]);
    float4 b0 = __ldg(&bp[lane * 2]), b1 = __ldg(&bp[lane * 2 + 1]);

    float es = v0.x*a0.x + v0.y*a0.y + v0.z*a0.z + v0.w*a0.w
             + v1.x*a1.x + v1.y*a1.y + v1.z*a1.z + v1.w*a1.w;
    float ed = v0.x*b0.x + v0.y*b0.y + v0.z*b0.z + v0.w*b0.w
             + v1.x*b1.x + v1.y*b1.y + v1.z*b1.z + v1.w*b1.w;

    // 8 lanes per head (lanes h*8..h*8+7 cover head h's 64 dims)
    #pragma unroll
    for (int o = 4; o; o >>= 1) {
        es += __shfl_xor_sync(0xffffffffu, es, o);
        ed += __shfl_xor_sync(0xffffffffu, ed, o);
    }
    if ((lane & 7) == 0) {
        int h = lane >> 3;
        g_es[w * NHEAD + h] = es;
        g_ed[w * NHEAD + h] = ed;
    }
}

__device__ __forceinline__ float lrelu(float v) { return v > 0.f ? v : NEG * v; }

// ---------------- aggregation: warp per dst node, local softmax ----------------
__global__ void __launch_bounds__(256) k_agg(const float* __restrict__ lin,
                                             const float* __restrict__ bias,
                                             float* __restrict__ out) {
    int n = (blockIdx.x * blockDim.x + threadIdx.x) >> 5;
    if (n >= NN) return;
    int lane = threadIdx.x & 31;

    int e0 = g_off[n], e1 = g_off[n + 1];
    float4 edv = ((const float4*)g_ed)[n];
    float edh[4] = {edv.x, edv.y, edv.z, edv.w};

    // pass A: per-head max of leaky_relu(es[src]+ed[dst])
    float m0 = -INFINITY, m1 = -INFINITY, m2 = -INFINITY, m3 = -INFINITY;
    for (int e = e0 + lane; e < e1; e += 32) {
        int s = g_csr_src[e];
        float4 ev = ((const float4*)g_es)[s];
        m0 = fmaxf(m0, lrelu(ev.x + edh[0]));
        m1 = fmaxf(m1, lrelu(ev.y + edh[1]));
        m2 = fmaxf(m2, lrelu(ev.z + edh[2]));
        m3 = fmaxf(m3, lrelu(ev.w + edh[3]));
    }
    #pragma unroll
    for (int o = 16; o; o >>= 1) {
        m0 = fmaxf(m0, __shfl_xor_sync(0xffffffffu, m0, o));
        m1 = fmaxf(m1, __shfl_xor_sync(0xffffffffu, m1, o));
        m2 = fmaxf(m2, __shfl_xor_sync(0xffffffffu, m2, o));
        m3 = fmaxf(m3, __shfl_xor_sync(0xffffffffu, m3, o));
    }

    int head = lane >> 3;                 // 8 lanes per head
    float mh = (head == 0) ? m0 : (head == 1) ? m1 : (head == 2) ? m2 : m3;
    float edme = edh[head];

    float a0=0,a1=0,a2=0,a3=0,a4=0,a5=0,a6=0,a7=0, den=0;
    const float4* lp4 = (const float4*)lin;

    int s_next = (e0 < e1) ? g_csr_src[e0] : 0;
    for (int e = e0; e < e1; e++) {
        int s = s_next;
        if (e + 1 < e1) s_next = g_csr_src[e + 1];
        float el = lrelu(g_es[s * NHEAD + head] + edme);
        float ex = __expf(el - mh);
        den += ex;
        float4 v0 = lp4[(size_t)s * 64 + lane * 2];
        float4 v1 = lp4[(size_t)s * 64 + lane * 2 + 1];
        a0 += ex * v0.x; a1 += ex * v0.y; a2 += ex * v0.z; a3 += ex * v0.w;
        a4 += ex * v1.x; a5 += ex * v1.y; a6 += ex * v1.z; a7 += ex * v1.w;
    }

    float inv = 1.f / (den + 1e-16f);
    const float4* bv = (const float4*)(bias + lane * 8);
    float4 bb0 = __ldg(&bv[0]), bb1 = __ldg(&bv[1]);
    float4 o0, o1;
    o0.x = fmaxf(a0 * inv + bb0.x, 0.f);
    o0.y = fmaxf(a1 * inv + bb0.y, 0.f);
    o0.z = fmaxf(a2 * inv + bb0.z, 0.f);
    o0.w = fmaxf(a3 * inv + bb0.w, 0.f);
    o1.x = fmaxf(a4 * inv + bb1.x, 0.f);
    o1.y = fmaxf(a5 * inv + bb1.y, 0.f);
    o1.z = fmaxf(a6 * inv + bb1.z, 0.f);
    o1.w = fmaxf(a7 * inv + bb1.w, 0.f);
    ((float4*)(out + (size_t)n * HH))[lane * 2]     = o0;
    ((float4*)(out + (size_t)n * HH))[lane * 2 + 1] = o1;
}

// ---------------- pooling: run-length partial sums over sorted batch ----------------
__global__ void k_cnt(const int* __restrict__ batch) {
    __shared__ float sh[GG];
    int t = threadIdx.x;
    if (t < GG) sh[t] = 0.f;
    __syncthreads();
    for (int n = blockIdx.x * blockDim.x + t; n < NN; n += gridDim.x * blockDim.x)
        atomicAdd(&sh[batch[n]], 1.f);
    __syncthreads();
    if (t < GG) atomicAdd(&g_cnt[t], sh[t]);
}

__global__ void k_pool(const float* __restrict__ x,
                       const int* __restrict__ batch) {
    int c = threadIdx.x;            // 0..127
    int cchunk = blockIdx.y;        // 0..4
    const float* base; int stride, coff, gcol;
    if      (cchunk == 0) { base = x;    stride = INCH; coff = c;       gcol = c;       }
    else if (cchunk == 1) { base = g_h1; stride = HH;   coff = c;       gcol = 128 + c; }
    else if (cchunk == 2) { base = g_h1; stride = HH;   coff = 128 + c; gcol = 256 + c; }
    else if (cchunk == 3) { base = g_h2; stride = HH;   coff = c;       gcol = 384 + c; }
    else                  { base = g_h2; stride = HH;   coff = 128 + c; gcol = 512 + c; }

    int n0 = blockIdx.x * 256;
    int n1 = min(n0 + 256, NN);
    float acc = 0.f; int curg = -1;
    for (int n = n0; n < n1; n++) {
        int g = batch[n];
        if (g != curg) {
            if (curg >= 0) atomicAdd(&g_pool[curg * DCAT + gcol], acc);
            acc = 0.f; curg = g;
        }
        acc += base[(size_t)n * stride + coff];
    }
    if (curg >= 0) atomicAdd(&g_pool[curg * DCAT + gcol], acc);
}

// ---------------- final MLP: [64,640] -> relu(256) -> 128 ----------------
__global__ void k_mlp(const float* __restrict__ W3, const float* __restrict__ b3,
                      const float* __restrict__ W4, const float* __restrict__ b4,
                      float* __restrict__ out) {
    int g = blockIdx.x;
    int t = threadIdx.x;  // 256
    __shared__ float p[DCAT];
    __shared__ float hm[256];
    float invc = 1.f / fmaxf(g_cnt[g], 1.f);
    for (int i = t; i < DCAT; i += 256) p[i] = g_pool[g * DCAT + i] * invc;
    __syncthreads();
    float acc = b3[t];
    for (int k = 0; k < DCAT; k++) acc += p[k] * W3[k * 256 + t];
    hm[t] = fmaxf(acc, 0.f);
    __syncthreads();
    if (t < 128) {
        float a2 = b4[t];
        for (int k = 0; k < 256; k++) a2 += hm[k] * W4[k * 128 + t];
        out[g * 128 + t] = a2;
    }
}

// ---------------- launch ----------------
extern "C" void kernel_launch(void* const* d_in, const int* in_sizes, int n_in,
                              void* d_out, int out_size) {
    const float* x     = (const float*)d_in[0];
    const int*   ei    = (const int*)d_in[1];     // int32! (JAX x64 disabled)
    const int*   batch = (const int*)d_in[2];     // int32!
    const float* W1  = (const float*)d_in[3];
    const float* a1s = (const float*)d_in[4];
    const float* a1d = (const float*)d_in[5];
    const float* b1  = (const float*)d_in[6];
    const float* W2  = (const float*)d_in[7];
    const float* a2s = (const float*)d_in[8];
    const float* a2d = (const float*)d_in[9];
    const float* b2  = (const float*)d_in[10];
    const float* W3  = (const float*)d_in[11];
    const float* b3  = (const float*)d_in[12];
    const float* W4  = (const float*)d_in[13];
    const float* b4  = (const float*)d_in[14];
    float* out = (float*)d_out;

    void *p_lin, *p_h1, *p_h2;
    cudaGetSymbolAddress(&p_lin, g_lin);
    cudaGetSymbolAddress(&p_h1,  g_h1);
    cudaGetSymbolAddress(&p_h2,  g_h2);
    float* lin = (float*)p_lin;
    float* h1  = (float*)p_h1;
    float* h2  = (float*)p_h2;

    cudaFuncSetAttribute(k_gemm<128>, cudaFuncAttributeMaxDynamicSharedMemorySize, 64 * 128 * 4);
    cudaFuncSetAttribute(k_gemm<256>, cudaFuncAttributeMaxDynamicSharedMemorySize, 64 * 256 * 4);

    // CSR build + zeroing
    k_zero<<<(NN + 255) / 256, 256>>>();
    k_hist<<<(NE + 255) / 256, 256>>>(ei);
    k_scan<<<1, 1024>>>();
    k_scatter<<<(NE + 255) / 256, 256>>>(ei);

    int gemm_blocks = (NN + 63) / 64;
    int warp_blocks = (NN * 32 + 255) / 256;

    // layer 1
    k_gemm<128><<<gemm_blocks, 256, 64 * 128 * 4>>>(x, W1, lin);
    k_logits<<<warp_blocks, 256>>>(lin, a1s, a1d);
    k_agg<<<warp_blocks, 256>>>(lin, b1, h1);

    // layer 2
    k_gemm<256><<<gemm_blocks, 256, 64 * 256 * 4>>>(h1, W2, lin);
    k_logits<<<warp_blocks, 256>>>(lin, a2s, a2d);
    k_agg<<<warp_blocks, 256>>>(lin, b2, h2);

    // pooling + MLP
    k_cnt<<<64, 256>>>(batch);
    dim3 pg((NN + 255) / 256, 5);
    k_pool<<<pg, 128>>>(x, batch);
    k_mlp<<<GG, 256>>>(W3, b3, W4, b4, out);
}